// round 12
// baseline (speedup 1.0000x reference)
#include <cuda_runtime.h>
#include <math.h>

// ---------------------------------------------------------------------------
// PathGuidedAggregator: S=8192 x P=16 x K=16, D=128, H=64
// Round 10: R9 + Phase-B retile to the LDS-count optimum (dq8/j4/p4:
// 32 LDS/thread vs 48) with BOTH R6 failure causes fixed:
//  - sAgg XOR quad swizzle (q ^ (row>>2)&3) kills the p/p+8 2-way conflict;
//    thread-side it folds to chunk index c^pgrp, keeping W1 loads uniform.
//  - two-stage dq reduction (dq4-7 store, sync, dq0-3 load+add+store) keeps
//    sPart at 4 banks = 16.9KB -> total SMEM 66.8KB (== R9), L1D preserved.
// Everything else identical to R9 (in-kernel zero + soft grid barrier,
// inline mask detect, prefetch, 456 persistent blocks).
// ---------------------------------------------------------------------------

#define DD 128
#define PP 16
#define KK 16
#define HH 64
#define AGG_STRIDE 132           // floats per sAgg row
#define PART_PSTRIDE 33          // ull per path row in sPart
#define PART_DQ (16 * PART_PSTRIDE)  // 528 ull per bank (4 banks)

__device__ int g_zero_done = 0;   // blocks that finished zeroing
__device__ int g_exit_cnt  = 0;   // blocks that finished the kernel

// ---- packed f32x2 helpers (sm_100+) ---------------------------------------
__device__ __forceinline__ unsigned long long pack2(float x, float y) {
    unsigned long long r;
    asm("mov.b64 %0, {%1, %2};" : "=l"(r) : "f"(x), "f"(y));
    return r;
}
__device__ __forceinline__ float2 unpack2(unsigned long long v) {
    float2 r;
    asm("mov.b64 {%0, %1}, %2;" : "=f"(r.x), "=f"(r.y) : "l"(v));
    return r;
}
__device__ __forceinline__ void fma2(unsigned long long& acc,
                                     unsigned long long a,
                                     unsigned long long b) {
    asm("fma.rn.f32x2 %0, %1, %2, %0;" : "+l"(acc) : "l"(a), "l"(b));
}
__device__ __forceinline__ unsigned long long add2(unsigned long long a,
                                                   unsigned long long b) {
    unsigned long long r;
    asm("add.rn.f32x2 %0, %1, %2;" : "=l"(r) : "l"(a), "l"(b));
    return r;
}

// Dynamic SMEM layout (float index):
//   sW1    [0     .. 8192)    32 KB  W1[d][j] row-major
//   sAgg0  [8192  .. 10304)   16 x 132 (quad-swizzled rows)
//   sAgg1  [10304 .. 12416)   16 x 132
//   sPart  [12416 .. 16640)   4 banks x 528 ull (16.9 KB)
//   sWgt   [16640 .. 16672)   2 x 16
//   sVal   [16672 .. 16704)   2 x 16 (int)
static const int SMEM_FLOATS = 16704;   // 66816 B

__global__ void __launch_bounds__(512, 3)
pga_kernel(const float* __restrict__ E, const float* __restrict__ W1,
           const float* __restrict__ b1, const float* __restrict__ W2,
           const float* __restrict__ b2, const int* __restrict__ sids,
           const int* __restrict__ eids, const void* __restrict__ maskp,
           float* __restrict__ out, int S, int out_n) {
    extern __shared__ float smem[];
    float* sW1  = smem;
    unsigned long long* sPart = (unsigned long long*)(smem + 12416);

    const int t = threadIdx.x;
    const int lane = t & 31;
    const int warp = t >> 5;
    const int grid = gridDim.x;

    // ---- Zero phase: grid-stride float4 zero of the output ---------------
    {
        float4 z = make_float4(0.f, 0.f, 0.f, 0.f);
        const int n4 = out_n >> 2;
        for (int i = blockIdx.x * 512 + t; i < n4; i += grid * 512)
            ((float4*)out)[i] = z;
        for (int i = (n4 << 2) + blockIdx.x * 512 + t; i < out_n; i += grid * 512)
            out[i] = 0.f;
        __syncthreads();
        if (t == 0) {
            __threadfence();
            atomicAdd(&g_zero_done, 1);
        }
    }

    // ---- Inline mask dtype detection (all blocks agree) -------------------
    int mode;
    {
        const unsigned* mw = (const unsigned*)maskp;
        unsigned v0 = __ldg(mw + t), v1 = __ldg(mw + 512 + t);
        int gt1 = ((v0 > 1u) && (v0 != 0x3F800000u)) ||
                  ((v1 > 1u) && (v1 != 0x3F800000u));
        int one = (v0 == 0x3F800000u) || (v1 == 0x3F800000u);
        int any_gt1 = __syncthreads_or(gt1);
        int any_one = __syncthreads_or(one);
        mode = any_gt1 ? 0 : (any_one ? 2 : 1);
    }

    // W1 -> smem (vectorized)
    {
        const float4* w4 = (const float4*)W1;
        #pragma unroll
        for (int i = t; i < DD * HH / 4; i += 512)
            ((float4*)sW1)[i] = __ldg(w4 + i);
    }
    // Phase C per-thread constants (indexed by lane only)
    const float rb1x = __ldg(b1 + 2 * lane);
    const float rb1y = __ldg(b1 + 2 * lane + 1);
    const float rw2x = __ldg(W2 + 2 * lane);
    const float rw2y = __ldg(W2 + 2 * lane + 1);
    const float bias2 = __ldg(b2);
    __syncthreads();

    // Phase B decomposition: t = dq*64 + jgrp*4 + pgrp
    const int dq   = t >> 6;        // 0..7  -> d in [dq*16, dq*16+16)
    const int jgrp = (t >> 2) & 15; // j = jgrp*4 .. +3
    const int pgrp = t & 3;         // paths pgrp*4 .. +3
    // Phase A/D swizzle for gather warp (path == warp):
    const int wsw = (warp >> 2) & 3;

    bool first = true;
    int buf = 0;
    for (int s = blockIdx.x; s < S; s += grid, buf ^= 1) {
        float* sAgg = smem + 8192 + buf * (PP * AGG_STRIDE);
        float* sWgt = smem + 16640 + buf * PP;
        int*   sVal = (int*)(smem + 16672) + buf * PP;

        // ---------------- Phase A: gather (warp p <-> path p) --------------
        {
            const int p = warp;
            const int base = (s * PP + p) * KK;
            const int4* ip = (const int4*)(eids + base);

            if (lane == 0 && s + grid < S) {
                const int nb = ((s + grid) * PP + p) * KK;
                asm volatile("prefetch.global.L1 [%0];" :: "l"(eids + nb));
                const char* mpc = (const char*)maskp +
                                  ((mode == 0) ? (size_t)nb : (size_t)nb * 4);
                asm volatile("prefetch.global.L1 [%0];" :: "l"(mpc));
            }

            unsigned mb = 0;
            if (mode == 0) {
                uint4 mv = __ldg((const uint4*)((const unsigned char*)maskp + base));
                unsigned wds[4] = {mv.x, mv.y, mv.z, mv.w};
                #pragma unroll
                for (int q = 0; q < 4; q++)
                    #pragma unroll
                    for (int b = 0; b < 4; b++)
                        mb |= (((wds[q] >> (8 * b)) & 0xFFu) ? 1u : 0u) << (q * 4 + b);
            } else if (mode == 1) {
                const int4* m4 = (const int4*)((const int*)maskp + base);
                #pragma unroll
                for (int q = 0; q < 4; q++) {
                    int4 mv = __ldg(m4 + q);
                    mb |= (mv.x ? 1u : 0u) << (q * 4 + 0);
                    mb |= (mv.y ? 1u : 0u) << (q * 4 + 1);
                    mb |= (mv.z ? 1u : 0u) << (q * 4 + 2);
                    mb |= (mv.w ? 1u : 0u) << (q * 4 + 3);
                }
            } else {
                const float4* m4 = (const float4*)((const float*)maskp + base);
                #pragma unroll
                for (int q = 0; q < 4; q++) {
                    float4 mv = __ldg(m4 + q);
                    mb |= (mv.x != 0.f ? 1u : 0u) << (q * 4 + 0);
                    mb |= (mv.y != 0.f ? 1u : 0u) << (q * 4 + 1);
                    mb |= (mv.z != 0.f ? 1u : 0u) << (q * 4 + 2);
                    mb |= (mv.w != 0.f ? 1u : 0u) << (q * 4 + 3);
                }
            }
            const int cnt = __popc(mb);

            const float4* E4 = (const float4*)E;
            float4 acc = make_float4(0.f, 0.f, 0.f, 0.f);
            #pragma unroll
            for (int h = 0; h < 2; h++) {
                int4 ia = __ldg(ip + 2 * h);
                int4 ib = __ldg(ip + 2 * h + 1);
                const int ids8[8] = {ia.x, ia.y, ia.z, ia.w, ib.x, ib.y, ib.z, ib.w};
                #pragma unroll
                for (int k = 0; k < 8; k++) {
                    if (mb & (1u << (8 * h + k))) {
                        float4 v = __ldg(E4 + ids8[k] * (DD / 4) + lane);
                        acc.x += v.x; acc.y += v.y; acc.z += v.z; acc.w += v.w;
                    }
                }
            }
            const float inv = 1.f / (float)(cnt > 0 ? cnt : 1);
            float4 a = make_float4(acc.x * inv, acc.y * inv, acc.z * inv, acc.w * inv);
            // swizzled store: logical quad 'lane' -> stored quad lane^wsw
            ((float4*)(sAgg + p * AGG_STRIDE))[lane ^ wsw] = a;
            if (lane == 0) sVal[p] = (cnt > 0);
        }
        __syncthreads();   // S1: sAgg(buf) ready

        // -------- Phase B stage 1: tiled GEMM partials (dq8/j4/p4) ----------
        unsigned long long hx0, hx1, hx2, hx3, hy0, hy1, hy2, hy3;
        {
            const int prow = pgrp * 4;
            const float* a0b = sAgg + (prow + 0) * AGG_STRIDE;
            const float* a1b = sAgg + (prow + 1) * AGG_STRIDE;
            const float* a2b = sAgg + (prow + 2) * AGG_STRIDE;
            const float* a3b = sAgg + (prow + 3) * AGG_STRIDE;
            hx0 = hx1 = hx2 = hx3 = 0ull;
            hy0 = hy1 = hy2 = hy3 = 0ull;
            #pragma unroll
            for (int c = 0; c < 4; c++) {
                // stored quad for logical chunk c of these rows: dq*4 + (c^pgrp)
                const int qf = (dq * 4 + (c ^ pgrp)) * 4;   // float offset
                float4 a0 = *(const float4*)(a0b + qf);
                float4 a1 = *(const float4*)(a1b + qf);
                float4 a2 = *(const float4*)(a2b + qf);
                float4 a3 = *(const float4*)(a3b + qf);
                const float av0[4] = {a0.x, a0.y, a0.z, a0.w};
                const float av1[4] = {a1.x, a1.y, a1.z, a1.w};
                const float av2[4] = {a2.x, a2.y, a2.z, a2.w};
                const float av3[4] = {a3.x, a3.y, a3.z, a3.w};
                const float* wrow = sW1 + (dq * 16 + c * 4) * HH + jgrp * 4;
                #pragma unroll
                for (int r = 0; r < 4; r++) {
                    ulonglong2 w = *(const ulonglong2*)(wrow + r * HH);
                    unsigned long long aa;
                    aa = pack2(av0[r], av0[r]); fma2(hx0, aa, w.x); fma2(hy0, aa, w.y);
                    aa = pack2(av1[r], av1[r]); fma2(hx1, aa, w.x); fma2(hy1, aa, w.y);
                    aa = pack2(av2[r], av2[r]); fma2(hx2, aa, w.x); fma2(hy2, aa, w.y);
                    aa = pack2(av3[r], av3[r]); fma2(hx3, aa, w.x); fma2(hy3, aa, w.y);
                }
            }
            // dq 4..7 store partials into bank (dq-4)
            if (dq >= 4) {
                unsigned long long* bk = sPart + (dq - 4) * PART_DQ;
                const int b0 = (prow) * PART_PSTRIDE + 2 * jgrp;
                bk[b0                    ] = hx0; bk[b0 + 1                ] = hy0;
                bk[b0 + PART_PSTRIDE     ] = hx1; bk[b0 + PART_PSTRIDE + 1 ] = hy1;
                bk[b0 + 2 * PART_PSTRIDE ] = hx2; bk[b0 + 2 * PART_PSTRIDE + 1] = hy2;
                bk[b0 + 3 * PART_PSTRIDE ] = hx3; bk[b0 + 3 * PART_PSTRIDE + 1] = hy3;
            }
        }
        __syncthreads();   // S2a: high-dq partials in sPart

        // -------- Phase B stage 2: dq 0..3 fold in partner's partials -------
        if (dq < 4) {
            unsigned long long* bk = sPart + dq * PART_DQ;
            const int b0 = (pgrp * 4) * PART_PSTRIDE + 2 * jgrp;
            hx0 = add2(hx0, bk[b0]);
            hy0 = add2(hy0, bk[b0 + 1]);
            hx1 = add2(hx1, bk[b0 + PART_PSTRIDE]);
            hy1 = add2(hy1, bk[b0 + PART_PSTRIDE + 1]);
            hx2 = add2(hx2, bk[b0 + 2 * PART_PSTRIDE]);
            hy2 = add2(hy2, bk[b0 + 2 * PART_PSTRIDE + 1]);
            hx3 = add2(hx3, bk[b0 + 3 * PART_PSTRIDE]);
            hy3 = add2(hy3, bk[b0 + 3 * PART_PSTRIDE + 1]);
            bk[b0                    ] = hx0; bk[b0 + 1                ] = hy0;
            bk[b0 + PART_PSTRIDE     ] = hx1; bk[b0 + PART_PSTRIDE + 1 ] = hy1;
            bk[b0 + 2 * PART_PSTRIDE ] = hx2; bk[b0 + 2 * PART_PSTRIDE + 1] = hy2;
            bk[b0 + 3 * PART_PSTRIDE ] = hx3; bk[b0 + 3 * PART_PSTRIDE + 1] = hy3;
        }
        __syncthreads();   // S2b: sPart holds 4 dq-pair sums

        // ------- Phase C: reduce 4 banks, bias+relu, dot W2, sigmoid -------
        {
            const int p = warp;
            float hx = 0.f, hy = 0.f;
            #pragma unroll
            for (int b = 0; b < 4; b++) {
                float2 v = unpack2(sPart[b * PART_DQ + p * PART_PSTRIDE + lane]);
                hx += v.x; hy += v.y;
            }
            float h0 = fmaxf(hx + rb1x, 0.f);
            float h1 = fmaxf(hy + rb1y, 0.f);
            float hw = h0 * rw2x + h1 * rw2y;
            #pragma unroll
            for (int o = 16; o; o >>= 1) hw += __shfl_xor_sync(0xffffffffu, hw, o);
            if (lane == 0) {
                float x = hw + bias2;
                float w = 1.f / (1.f + __expf(-x));
                sWgt[p] = sVal[p] ? w : 0.f;
            }
        }
        __syncthreads();   // S3: sWgt ready

        // ---- soft grid barrier before the FIRST output write only --------
        if (first) {
            if (t == 0) {
                while (atomicAdd(&g_zero_done, 0) < grid) { }
            }
            __syncthreads();
            first = false;
        }

        // -------- Phase D: weighted mean + scatter (overlaps next gather) ---
        if (t < DD) {
            float o = 0.f;
            int nv = 0;
            const int tq = t >> 2, tr = t & 3;
            #pragma unroll
            for (int p = 0; p < PP; p++) {
                const int f = ((tq ^ ((p >> 2) & 3)) << 2) + tr;  // de-swizzle
                o += sWgt[p] * sAgg[p * AGG_STRIDE + f];
                nv += sVal[p];
            }
            out[__ldg(sids + s) * DD + t] = o / (float)(nv > 0 ? nv : 1);
        }
        // no end-of-node sync (double-buffered; sPart fenced by S1..S2b next).
    }

    // ---- reset counters for deterministic graph replay --------------------
    __syncthreads();
    if (t == 0) {
        __threadfence();
        int d = atomicAdd(&g_exit_cnt, 1);
        if (d == grid - 1) {
            g_zero_done = 0;
            g_exit_cnt  = 0;
        }
    }
}

extern "C" void kernel_launch(void* const* d_in, const int* in_sizes, int n_in,
                              void* d_out, int out_size) {
    const float* E   = (const float*)d_in[0];
    const float* W1  = (const float*)d_in[1];
    const float* b1  = (const float*)d_in[2];
    const float* W2  = (const float*)d_in[3];
    const float* b2  = (const float*)d_in[4];
    const int*   sid = (const int*)d_in[5];
    const int*   eid = (const int*)d_in[6];
    const void*  msk = d_in[7];
    float* out = (float*)d_out;

    const int S = in_sizes[5];

    static const int SMEM_BYTES = SMEM_FLOATS * 4; // 66816 B
    cudaFuncSetAttribute(pga_kernel, cudaFuncAttributeMaxDynamicSharedMemorySize,
                         SMEM_BYTES);

    // 152 SMs x 3 blocks/SM = 456 blocks — exactly co-resident (soft barrier).
    int grid = 456;
    pga_kernel<<<grid, 512, SMEM_BYTES>>>(E, W1, b1, W2, b2, sid, eid, msk,
                                          out, S, out_size);
}